// round 6
// baseline (speedup 1.0000x reference)
#include <cuda_runtime.h>

// AUGRU persistent kernel. B=2048 rows, T=200 steps, D=64.
// 128 CTAs x 16 rows, 512 threads (4 warps/SMSP), split-K across thread halves.
// Weights + h-state resident in SMEM.

#define TT   200
#define DD   64
#define BC   16     // batch rows per CTA
#define PAD  20     // padded row stride (floats) for transposed activation tiles
#define NTHR 512

// SMEM layout (float offsets)
#define OFF_WG   0                      // W_gate   128*128
#define OFF_WC   16384                  // W_cand   128*64
#define OFF_BG   24576                  // b_gate   128
#define OFF_BC   24704                  // b_cand   64
#define OFF_ATT  24768                  // att      16*200
#define OFF_XT   27968                  // x tile   2 * 64 * PAD (double-buffered, transposed [d][r])
#define OFF_HT   (OFF_XT + 2*64*PAD)    // h        64 * PAD (transposed [j][r])
#define OFF_RHT  (OFF_HT + 64*PAD)      // r*h      64 * PAD
#define OFF_UT   (OFF_RHT + 64*PAD)     // u_att    64 * PAD
#define OFF_SL   (OFF_UT + 64*PAD)      // seqlen   16 (int)
#define OFF_PG   (OFF_SL + 16)          // gates partials 16*128 (layout [r*128+gj])
#define OFF_PC   (OFF_PG + 16*128)      // cand  partials 16*64  (layout [r*64+cj])
#define SMEM_FLOATS (OFF_PC + 16*64)
#define SMEM_BYTES  (SMEM_FLOATS * 4)

__global__ void augru_zero_kernel(float* __restrict__ out, int n4) {
    int i = blockIdx.x * blockDim.x + threadIdx.x;
    if (i < n4) {
        ((float4*)out)[i] = make_float4(0.f, 0.f, 0.f, 0.f);
    }
}

__global__ void __launch_bounds__(NTHR, 1) augru_kernel(
    const float* __restrict__ x,       // [B, T, 64]
    const int*   __restrict__ seqlen,  // [B, 1]
    const float* __restrict__ att,     // [B, T, 1]
    const float* __restrict__ Wg,      // [128, 128]
    const float* __restrict__ bg,      // [128]
    const float* __restrict__ Wc,      // [128, 64]
    const float* __restrict__ bc,      // [64]
    float* __restrict__ out)           // [B, T, 64]
{
    extern __shared__ float sm[];
    const int tx   = threadIdx.x;
    const int row0 = blockIdx.x * BC;

    // ---------------- prologue: load weights / biases / att / seqlen ----------------
    for (int i = tx; i < 128 * 128; i += NTHR) sm[OFF_WG + i] = Wg[i];
    for (int i = tx; i < 128 * 64;  i += NTHR) sm[OFF_WC + i] = Wc[i];
    for (int i = tx; i < 128;       i += NTHR) sm[OFF_BG + i] = bg[i];
    for (int i = tx; i < 64;        i += NTHR) sm[OFF_BC + i] = bc[i];
    for (int i = tx; i < BC * TT;   i += NTHR) {
        int r = i / TT, t = i % TT;
        sm[OFF_ATT + i] = att[(size_t)(row0 + r) * TT + t];
    }
    for (int i = tx; i < 64 * PAD;  i += NTHR) sm[OFF_HT + i] = 0.f;
    if (tx < BC) ((int*)(sm + OFF_SL))[tx] = seqlen[row0 + tx];

    // ---------------- preload x(t=0) into xT buffer 0 (transposed) ----------------
    const bool xld = (tx < 256);
    const int rx = (tx & 255) >> 4;    // 0..15 (row)
    const int d0 = (tx & 15) * 4;      // 0,4,..,60
    const float* xpf = x + ((size_t)(row0 + (xld ? rx : 0)) * TT) * DD + d0;
    if (xld) {
        float4 p = *(const float4*)xpf;
        float* xw = sm + OFF_XT;       // buffer 0
        xw[(d0 + 0) * PAD + rx] = p.x;
        xw[(d0 + 1) * PAD + rx] = p.y;
        xw[(d0 + 2) * PAD + rx] = p.z;
        xw[(d0 + 3) * PAD + rx] = p.w;
    }
    __syncthreads();

    const int* sl = (const int*)(sm + OFF_SL);
    int ml = 0;
    #pragma unroll
    for (int i = 0; i < BC; i++) ml = max(ml, sl[i]);

    // gates tiling: 1 column x 8 rows x half-K per thread
    const int gj  = tx & 127;              // gate column 0..127
    const int gr8 = ((tx >> 7) & 1) * 8;   // row base: 0 or 8
    const int kh  = tx >> 8;               // k-half: 0 (x part) / 1 (h part)
    // cand tiling: 1 column x 4 rows x half-K per thread
    const int cj  = tx & 63;               // cand column 0..63
    const int cr4 = ((tx >> 6) & 3) * 4;   // row base: 0,4,8,12

    const float* wgcol = sm + OFF_WG + (kh * 64) * 128 + gj;
    const float* wccol = sm + OFF_WC + (kh * 64) * 64  + cj;

    for (int t = 0; t < ml; ++t) {
        const float* xb = sm + OFF_XT + (t & 1) * 64 * PAD;
        const float* gvb = kh ? (sm + OFF_HT)  : xb;   // gates operand for this k-half
        const float* cvb = kh ? (sm + OFF_RHT) : xb;   // cand  operand for this k-half

        // prefetch next x tile into registers (lands during gates GEMM)
        float4 q;
        const bool pf = (t + 1 < ml) && xld;
        if (pf) {
            q = *(const float4*)(xpf + (size_t)(t + 1) * DD);
        }

        // ------- stage 1: gates partial GEMM over this thread's k-half -------
        float a0 = 0.f, a1 = 0.f, a2 = 0.f, a3 = 0.f;
        float a4 = 0.f, a5 = 0.f, a6 = 0.f, a7 = 0.f;

        #pragma unroll 8
        for (int k = 0; k < 64; k++) {
            float  w  = wgcol[k * 128];
            float4 v0 = *(const float4*)(gvb + k * PAD + gr8);
            float4 v1 = *(const float4*)(gvb + k * PAD + gr8 + 4);
            a0 += v0.x * w; a1 += v0.y * w; a2 += v0.z * w; a3 += v0.w * w;
            a4 += v1.x * w; a5 += v1.y * w; a6 += v1.z * w; a7 += v1.w * w;
        }

        // ------- stage 2: k-half 1 publishes partials -------
        if (kh) {
            float* pg = sm + OFF_PG + gj;
            pg[(gr8 + 0) * 128] = a0; pg[(gr8 + 1) * 128] = a1;
            pg[(gr8 + 2) * 128] = a2; pg[(gr8 + 3) * 128] = a3;
            pg[(gr8 + 4) * 128] = a4; pg[(gr8 + 5) * 128] = a5;
            pg[(gr8 + 6) * 128] = a6; pg[(gr8 + 7) * 128] = a7;
        }
        __syncthreads();

        // ------- stage 3: k-half 0 reduces + sigmoid + scatter r*h / att*u -------
        if (!kh) {
            const float* pg = sm + OFF_PG + gj;
            a0 += pg[(gr8 + 0) * 128]; a1 += pg[(gr8 + 1) * 128];
            a2 += pg[(gr8 + 2) * 128]; a3 += pg[(gr8 + 3) * 128];
            a4 += pg[(gr8 + 4) * 128]; a5 += pg[(gr8 + 5) * 128];
            a6 += pg[(gr8 + 6) * 128]; a7 += pg[(gr8 + 7) * 128];

            const float bgi = sm[OFF_BG + gj];
            float g[8] = {a0, a1, a2, a3, a4, a5, a6, a7};
            float s[8];
            #pragma unroll
            for (int i = 0; i < 8; i++)
                s[i] = 1.f / (1.f + __expf(-(g[i] + bgi)));

            if (gj < 64) {
                float4 h0 = *(const float4*)(sm + OFF_HT + gj * PAD + gr8);
                float4 h1 = *(const float4*)(sm + OFF_HT + gj * PAD + gr8 + 4);
                float4 o0 = make_float4(s[0] * h0.x, s[1] * h0.y, s[2] * h0.z, s[3] * h0.w);
                float4 o1 = make_float4(s[4] * h1.x, s[5] * h1.y, s[6] * h1.z, s[7] * h1.w);
                *(float4*)(sm + OFF_RHT + gj * PAD + gr8)     = o0;
                *(float4*)(sm + OFF_RHT + gj * PAD + gr8 + 4) = o1;
            } else {
                const int uj = gj - 64;
                float4 o0, o1;
                o0.x = s[0] * sm[OFF_ATT + (gr8 + 0) * TT + t];
                o0.y = s[1] * sm[OFF_ATT + (gr8 + 1) * TT + t];
                o0.z = s[2] * sm[OFF_ATT + (gr8 + 2) * TT + t];
                o0.w = s[3] * sm[OFF_ATT + (gr8 + 3) * TT + t];
                o1.x = s[4] * sm[OFF_ATT + (gr8 + 4) * TT + t];
                o1.y = s[5] * sm[OFF_ATT + (gr8 + 5) * TT + t];
                o1.z = s[6] * sm[OFF_ATT + (gr8 + 6) * TT + t];
                o1.w = s[7] * sm[OFF_ATT + (gr8 + 7) * TT + t];
                *(float4*)(sm + OFF_UT + uj * PAD + gr8)     = o0;
                *(float4*)(sm + OFF_UT + uj * PAD + gr8 + 4) = o1;
            }
        }
        __syncthreads();

        // ------- stage 4: cand partial GEMM over this thread's k-half -------
        float c0 = 0.f, c1 = 0.f, c2 = 0.f, c3 = 0.f;

        #pragma unroll 8
        for (int k = 0; k < 64; k++) {
            float  w = wccol[k * 64];
            float4 v = *(const float4*)(cvb + k * PAD + cr4);
            c0 += v.x * w; c1 += v.y * w; c2 += v.z * w; c3 += v.w * w;
        }

        // ------- stage 5: k-half 1 publishes cand partials -------
        if (kh) {
            float* pc = sm + OFF_PC + cj;
            pc[(cr4 + 0) * 64] = c0; pc[(cr4 + 1) * 64] = c1;
            pc[(cr4 + 2) * 64] = c2; pc[(cr4 + 3) * 64] = c3;
        }
        __syncthreads();

        // ------- stage 6: k-half 0 reduces + tanh + AUGRU update -------
        if (!kh) {
            const float* pc = sm + OFF_PC + cj;
            c0 += pc[(cr4 + 0) * 64]; c1 += pc[(cr4 + 1) * 64];
            c2 += pc[(cr4 + 2) * 64]; c3 += pc[(cr4 + 3) * 64];

            const float bcj = sm[OFF_BC + cj];
            float4 hv = *(const float4*)(sm + OFF_HT + cj * PAD + cr4);
            float4 ua = *(const float4*)(sm + OFF_UT + cj * PAD + cr4);
            float cc[4] = {c0, c1, c2, c3};
            float hh[4] = {hv.x, hv.y, hv.z, hv.w};
            float uu[4] = {ua.x, ua.y, ua.z, ua.w};
            float hs[4], os[4];
            #pragma unroll
            for (int i = 0; i < 4; i++) {
                float cv = tanhf(cc[i] + bcj);
                float hn = (1.f - uu[i]) * hh[i] + uu[i] * cv;
                bool valid = (t < sl[cr4 + i]);
                hs[i] = valid ? hn : hh[i];
                os[i] = valid ? hn : 0.f;
            }
            *(float4*)(sm + OFF_HT + cj * PAD + cr4) =
                make_float4(hs[0], hs[1], hs[2], hs[3]);
            #pragma unroll
            for (int i = 0; i < 4; i++) {
                out[((size_t)(row0 + cr4 + i) * TT + t) * DD + cj] = os[i];
            }
        }

        // store prefetched x into the other buffer (read after the sync below)
        if (pf) {
            float* xw = sm + OFF_XT + ((t + 1) & 1) * 64 * PAD;
            xw[(d0 + 0) * PAD + rx] = q.x;
            xw[(d0 + 1) * PAD + rx] = q.y;
            xw[(d0 + 2) * PAD + rx] = q.z;
            xw[(d0 + 3) * PAD + rx] = q.w;
        }
        __syncthreads();
    }
}

extern "C" void kernel_launch(void* const* d_in, const int* in_sizes, int n_in,
                              void* d_out, int out_size) {
    const float* x      = (const float*)d_in[0];
    const int*   seqlen = (const int*)  d_in[1];
    const float* att    = (const float*)d_in[2];
    const float* Wg     = (const float*)d_in[3];
    const float* bg     = (const float*)d_in[4];
    const float* Wc     = (const float*)d_in[5];
    const float* bc     = (const float*)d_in[6];
    float* out = (float*)d_out;

    const int B = in_sizes[0] / (TT * DD);   // 2048

    // zero the output (positions past seq_len must be exactly 0)
    {
        int n4 = out_size / 4;
        int blk = 256;
        int grd = (n4 + blk - 1) / blk;
        augru_zero_kernel<<<grd, blk>>>(out, n4);
    }

    cudaFuncSetAttribute(augru_kernel, cudaFuncAttributeMaxDynamicSharedMemorySize, SMEM_BYTES);
    augru_kernel<<<B / BC, NTHR, SMEM_BYTES>>>(x, seqlen, att, Wg, bg, Wc, bc, out);
}

// round 7
// speedup vs baseline: 1.0181x; 1.0181x over previous
#include <cuda_runtime.h>

// AUGRU persistent kernel. B=2048 rows, T=200 steps, D=64.
// 128 CTAs x 16 rows, 256 threads. Batched-operand GEMM loops for high MLP.
// Weights + h-state resident in SMEM.

#define TT   200
#define DD   64
#define BC   16     // batch rows per CTA
#define PAD  20     // padded row stride (floats) for transposed activation tiles
#define NTHR 256

// SMEM layout (float offsets)
#define OFF_WG   0                      // W_gate   128*128
#define OFF_WC   16384                  // W_cand   128*64
#define OFF_BG   24576                  // b_gate   128
#define OFF_BC   24704                  // b_cand   64
#define OFF_ATT  24768                  // att      16*200
#define OFF_XT   27968                  // x tile   2 * 64 * PAD (double-buffered, transposed [d][r])
#define OFF_HT   (OFF_XT + 2*64*PAD)    // h        64 * PAD (transposed [j][r])
#define OFF_RHT  (OFF_HT + 64*PAD)      // r*h      64 * PAD
#define OFF_UT   (OFF_RHT + 64*PAD)     // u_att    64 * PAD
#define OFF_SL   (OFF_UT + 64*PAD)      // seqlen   16 (int)
#define SMEM_FLOATS (OFF_SL + 16)
#define SMEM_BYTES  (SMEM_FLOATS * 4)

__device__ __forceinline__ float fast_sigmoid(float z) {
    return 1.f / (1.f + __expf(-z));
}
__device__ __forceinline__ float fast_tanh(float z) {
    return 2.f / (1.f + __expf(-2.f * z)) - 1.f;
}

__global__ void augru_zero_kernel(float* __restrict__ out, int n4) {
    int i = blockIdx.x * blockDim.x + threadIdx.x;
    if (i < n4) {
        ((float4*)out)[i] = make_float4(0.f, 0.f, 0.f, 0.f);
    }
}

__global__ void __launch_bounds__(NTHR, 1) augru_kernel(
    const float* __restrict__ x,       // [B, T, 64]
    const int*   __restrict__ seqlen,  // [B, 1]
    const float* __restrict__ att,     // [B, T, 1]
    const float* __restrict__ Wg,      // [128, 128]
    const float* __restrict__ bg,      // [128]
    const float* __restrict__ Wc,      // [128, 64]
    const float* __restrict__ bc,      // [64]
    float* __restrict__ out)           // [B, T, 64]
{
    extern __shared__ float sm[];
    const int tx   = threadIdx.x;
    const int row0 = blockIdx.x * BC;

    // ---------------- prologue: load weights / biases / att / seqlen ----------------
    for (int i = tx; i < 128 * 128; i += NTHR) sm[OFF_WG + i] = Wg[i];
    for (int i = tx; i < 128 * 64;  i += NTHR) sm[OFF_WC + i] = Wc[i];
    for (int i = tx; i < 128;       i += NTHR) sm[OFF_BG + i] = bg[i];
    for (int i = tx; i < 64;        i += NTHR) sm[OFF_BC + i] = bc[i];
    for (int i = tx; i < BC * TT;   i += NTHR) {
        int r = i / TT, t = i % TT;
        sm[OFF_ATT + i] = att[(size_t)(row0 + r) * TT + t];
    }
    for (int i = tx; i < 64 * PAD;  i += NTHR) sm[OFF_HT + i] = 0.f;
    if (tx < BC) ((int*)(sm + OFF_SL))[tx] = seqlen[row0 + tx];

    // ---------------- preload x(t=0) into xT buffer 0 (transposed) ----------------
    const int rx = tx >> 4;            // 0..15 (row)
    const int d0 = (tx & 15) * 4;      // 0,4,..,60
    const float* xpf = x + ((size_t)(row0 + rx) * TT) * DD + d0;   // prefetch base
    {
        float4 p = *(const float4*)xpf;
        float* xw = sm + OFF_XT;       // buffer 0
        xw[(d0 + 0) * PAD + rx] = p.x;
        xw[(d0 + 1) * PAD + rx] = p.y;
        xw[(d0 + 2) * PAD + rx] = p.z;
        xw[(d0 + 3) * PAD + rx] = p.w;
    }
    __syncthreads();

    const int* sl = (const int*)(sm + OFF_SL);
    int ml = 0;
    #pragma unroll
    for (int i = 0; i < BC; i++) ml = max(ml, sl[i]);

    // gates tiling: each thread owns 1 column x 8 rows
    const int gj  = tx & 127;          // gate column 0..127
    const int gr8 = (tx >> 7) * 8;     // row base: 0 or 8
    // cand tiling: each thread owns 1 column x 4 rows
    const int cj  = tx & 63;           // cand column 0..63
    const int cr4 = (tx >> 6) * 4;     // row base: 0,4,8,12

    const float* wgcol = sm + OFF_WG + gj;
    const float* wccol = sm + OFF_WC + cj;

    for (int t = 0; t < ml; ++t) {
        const float* xb = sm + OFF_XT + (t & 1) * 64 * PAD;

        // prefetch next x tile into registers (lands during gates GEMM)
        float4 q;
        const bool pf = (t + 1 < ml);
        if (pf) {
            q = *(const float4*)(xpf + (size_t)(t + 1) * DD);
        }

        // ---------------- gates GEMM: [16 x 128] = [16 x 128(x,h)] @ Wg ----------------
        float a0 = 0.f, a1 = 0.f, a2 = 0.f, a3 = 0.f;
        float a4 = 0.f, a5 = 0.f, a6 = 0.f, a7 = 0.f;

        // x part: batched loads (12 LDS) then 32 FFMAs per 4-k group
        #pragma unroll 4
        for (int k0 = 0; k0 < 64; k0 += 4) {
            float w0 = wgcol[(k0 + 0) * 128];
            float w1 = wgcol[(k0 + 1) * 128];
            float w2 = wgcol[(k0 + 2) * 128];
            float w3 = wgcol[(k0 + 3) * 128];
            float4 p00 = *(const float4*)(xb + (k0 + 0) * PAD + gr8);
            float4 p01 = *(const float4*)(xb + (k0 + 0) * PAD + gr8 + 4);
            float4 p10 = *(const float4*)(xb + (k0 + 1) * PAD + gr8);
            float4 p11 = *(const float4*)(xb + (k0 + 1) * PAD + gr8 + 4);
            float4 p20 = *(const float4*)(xb + (k0 + 2) * PAD + gr8);
            float4 p21 = *(const float4*)(xb + (k0 + 2) * PAD + gr8 + 4);
            float4 p30 = *(const float4*)(xb + (k0 + 3) * PAD + gr8);
            float4 p31 = *(const float4*)(xb + (k0 + 3) * PAD + gr8 + 4);
            a0 += p00.x * w0; a1 += p00.y * w0; a2 += p00.z * w0; a3 += p00.w * w0;
            a4 += p01.x * w0; a5 += p01.y * w0; a6 += p01.z * w0; a7 += p01.w * w0;
            a0 += p10.x * w1; a1 += p10.y * w1; a2 += p10.z * w1; a3 += p10.w * w1;
            a4 += p11.x * w1; a5 += p11.y * w1; a6 += p11.z * w1; a7 += p11.w * w1;
            a0 += p20.x * w2; a1 += p20.y * w2; a2 += p20.z * w2; a3 += p20.w * w2;
            a4 += p21.x * w2; a5 += p21.y * w2; a6 += p21.z * w2; a7 += p21.w * w2;
            a0 += p30.x * w3; a1 += p30.y * w3; a2 += p30.z * w3; a3 += p30.w * w3;
            a4 += p31.x * w3; a5 += p31.y * w3; a6 += p31.z * w3; a7 += p31.w * w3;
        }
        // h part
        const float* hb = sm + OFF_HT;
        #pragma unroll 4
        for (int k0 = 0; k0 < 64; k0 += 4) {
            float w0 = wgcol[(k0 + 64) * 128];
            float w1 = wgcol[(k0 + 65) * 128];
            float w2 = wgcol[(k0 + 66) * 128];
            float w3 = wgcol[(k0 + 67) * 128];
            float4 p00 = *(const float4*)(hb + (k0 + 0) * PAD + gr8);
            float4 p01 = *(const float4*)(hb + (k0 + 0) * PAD + gr8 + 4);
            float4 p10 = *(const float4*)(hb + (k0 + 1) * PAD + gr8);
            float4 p11 = *(const float4*)(hb + (k0 + 1) * PAD + gr8 + 4);
            float4 p20 = *(const float4*)(hb + (k0 + 2) * PAD + gr8);
            float4 p21 = *(const float4*)(hb + (k0 + 2) * PAD + gr8 + 4);
            float4 p30 = *(const float4*)(hb + (k0 + 3) * PAD + gr8);
            float4 p31 = *(const float4*)(hb + (k0 + 3) * PAD + gr8 + 4);
            a0 += p00.x * w0; a1 += p00.y * w0; a2 += p00.z * w0; a3 += p00.w * w0;
            a4 += p01.x * w0; a5 += p01.y * w0; a6 += p01.z * w0; a7 += p01.w * w0;
            a0 += p10.x * w1; a1 += p10.y * w1; a2 += p10.z * w1; a3 += p10.w * w1;
            a4 += p11.x * w1; a5 += p11.y * w1; a6 += p11.z * w1; a7 += p11.w * w1;
            a0 += p20.x * w2; a1 += p20.y * w2; a2 += p20.z * w2; a3 += p20.w * w2;
            a4 += p21.x * w2; a5 += p21.y * w2; a6 += p21.z * w2; a7 += p21.w * w2;
            a0 += p30.x * w3; a1 += p30.y * w3; a2 += p30.z * w3; a3 += p30.w * w3;
            a4 += p31.x * w3; a5 += p31.y * w3; a6 += p31.z * w3; a7 += p31.w * w3;
        }

        // sigmoid + scatter: r-gates -> r*h, u-gates -> att*u
        {
            const float bgi = sm[OFF_BG + gj];
            float g[8] = {a0, a1, a2, a3, a4, a5, a6, a7};
            float s[8];
            #pragma unroll
            for (int i = 0; i < 8; i++)
                s[i] = fast_sigmoid(g[i] + bgi);

            if (gj < 64) {
                float4 h0 = *(const float4*)(sm + OFF_HT + gj * PAD + gr8);
                float4 h1 = *(const float4*)(sm + OFF_HT + gj * PAD + gr8 + 4);
                float4 o0 = make_float4(s[0] * h0.x, s[1] * h0.y, s[2] * h0.z, s[3] * h0.w);
                float4 o1 = make_float4(s[4] * h1.x, s[5] * h1.y, s[6] * h1.z, s[7] * h1.w);
                *(float4*)(sm + OFF_RHT + gj * PAD + gr8)     = o0;
                *(float4*)(sm + OFF_RHT + gj * PAD + gr8 + 4) = o1;
            } else {
                const int uj = gj - 64;
                float4 o0, o1;
                o0.x = s[0] * sm[OFF_ATT + (gr8 + 0) * TT + t];
                o0.y = s[1] * sm[OFF_ATT + (gr8 + 1) * TT + t];
                o0.z = s[2] * sm[OFF_ATT + (gr8 + 2) * TT + t];
                o0.w = s[3] * sm[OFF_ATT + (gr8 + 3) * TT + t];
                o1.x = s[4] * sm[OFF_ATT + (gr8 + 4) * TT + t];
                o1.y = s[5] * sm[OFF_ATT + (gr8 + 5) * TT + t];
                o1.z = s[6] * sm[OFF_ATT + (gr8 + 6) * TT + t];
                o1.w = s[7] * sm[OFF_ATT + (gr8 + 7) * TT + t];
                *(float4*)(sm + OFF_UT + uj * PAD + gr8)     = o0;
                *(float4*)(sm + OFF_UT + uj * PAD + gr8 + 4) = o1;
            }
        }
        __syncthreads();

        // ---------------- cand GEMM: [16 x 64] = [16 x 128(x, r*h)] @ Wc ----------------
        float c0 = 0.f, c1 = 0.f, c2 = 0.f, c3 = 0.f;

        #pragma unroll 4
        for (int k0 = 0; k0 < 64; k0 += 4) {
            float w0 = wccol[(k0 + 0) * 64];
            float w1 = wccol[(k0 + 1) * 64];
            float w2 = wccol[(k0 + 2) * 64];
            float w3 = wccol[(k0 + 3) * 64];
            float4 p0 = *(const float4*)(xb + (k0 + 0) * PAD + cr4);
            float4 p1 = *(const float4*)(xb + (k0 + 1) * PAD + cr4);
            float4 p2 = *(const float4*)(xb + (k0 + 2) * PAD + cr4);
            float4 p3 = *(const float4*)(xb + (k0 + 3) * PAD + cr4);
            c0 += p0.x * w0; c1 += p0.y * w0; c2 += p0.z * w0; c3 += p0.w * w0;
            c0 += p1.x * w1; c1 += p1.y * w1; c2 += p1.z * w1; c3 += p1.w * w1;
            c0 += p2.x * w2; c1 += p2.y * w2; c2 += p2.z * w2; c3 += p2.w * w2;
            c0 += p3.x * w3; c1 += p3.y * w3; c2 += p3.z * w3; c3 += p3.w * w3;
        }
        const float* rb = sm + OFF_RHT;
        #pragma unroll 4
        for (int k0 = 0; k0 < 64; k0 += 4) {
            float w0 = wccol[(k0 + 64) * 64];
            float w1 = wccol[(k0 + 65) * 64];
            float w2 = wccol[(k0 + 66) * 64];
            float w3 = wccol[(k0 + 67) * 64];
            float4 p0 = *(const float4*)(rb + (k0 + 0) * PAD + cr4);
            float4 p1 = *(const float4*)(rb + (k0 + 1) * PAD + cr4);
            float4 p2 = *(const float4*)(rb + (k0 + 2) * PAD + cr4);
            float4 p3 = *(const float4*)(rb + (k0 + 3) * PAD + cr4);
            c0 += p0.x * w0; c1 += p0.y * w0; c2 += p0.z * w0; c3 += p0.w * w0;
            c0 += p1.x * w1; c1 += p1.y * w1; c2 += p1.z * w1; c3 += p1.w * w1;
            c0 += p2.x * w2; c1 += p2.y * w2; c2 += p2.z * w2; c3 += p2.w * w2;
            c0 += p3.x * w3; c1 += p3.y * w3; c2 += p3.z * w3; c3 += p3.w * w3;
        }

        // tanh + AUGRU update + masked state/output (masks folded into values)
        {
            const float bcj = sm[OFF_BC + cj];
            float4 hv = *(const float4*)(sm + OFF_HT + cj * PAD + cr4);
            float4 ua = *(const float4*)(sm + OFF_UT + cj * PAD + cr4);
            float cc[4] = {c0, c1, c2, c3};
            float hh[4] = {hv.x, hv.y, hv.z, hv.w};
            float uu[4] = {ua.x, ua.y, ua.z, ua.w};
            float hs[4], os[4];
            #pragma unroll
            for (int i = 0; i < 4; i++) {
                float cv = fast_tanh(cc[i] + bcj);
                float hn = (1.f - uu[i]) * hh[i] + uu[i] * cv;
                bool valid = (t < sl[cr4 + i]);
                hs[i] = valid ? hn : hh[i];
                os[i] = valid ? hn : 0.f;
            }
            *(float4*)(sm + OFF_HT + cj * PAD + cr4) =
                make_float4(hs[0], hs[1], hs[2], hs[3]);
            #pragma unroll
            for (int i = 0; i < 4; i++) {
                out[((size_t)(row0 + cr4 + i) * TT + t) * DD + cj] = os[i];
            }
        }

        // store prefetched x into the other buffer (read after the sync below)
        if (pf) {
            float* xw = sm + OFF_XT + ((t + 1) & 1) * 64 * PAD;
            xw[(d0 + 0) * PAD + rx] = q.x;
            xw[(d0 + 1) * PAD + rx] = q.y;
            xw[(d0 + 2) * PAD + rx] = q.z;
            xw[(d0 + 3) * PAD + rx] = q.w;
        }
        __syncthreads();
    }
}

extern "C" void kernel_launch(void* const* d_in, const int* in_sizes, int n_in,
                              void* d_out, int out_size) {
    const float* x      = (const float*)d_in[0];
    const int*   seqlen = (const int*)  d_in[1];
    const float* att    = (const float*)d_in[2];
    const float* Wg     = (const float*)d_in[3];
    const float* bg     = (const float*)d_in[4];
    const float* Wc     = (const float*)d_in[5];
    const float* bc     = (const float*)d_in[6];
    float* out = (float*)d_out;

    const int B = in_sizes[0] / (TT * DD);   // 2048

    // zero the output (positions past seq_len must be exactly 0)
    {
        int n4 = out_size / 4;
        int blk = 256;
        int grd = (n4 + blk - 1) / blk;
        augru_zero_kernel<<<grd, blk>>>(out, n4);
    }

    cudaFuncSetAttribute(augru_kernel, cudaFuncAttributeMaxDynamicSharedMemorySize, SMEM_BYTES);
    augru_kernel<<<B / BC, NTHR, SMEM_BYTES>>>(x, seqlen, att, Wg, bg, Wc, bc, out);
}